// round 6
// baseline (speedup 1.0000x reference)
#include <cuda_runtime.h>
#include <cuda_fp16.h>
#include <cstdint>

// out[n,m,o] = sum_k sum_f x[n, idx[m,k], f] * iv[m,k] * W[k,f,o] + bias[o]
// N=16, M=65536, FIN=FOUT=32, K=7
static constexpr int N_ = 16, M_ = 65536, K_ = 7;
static constexpr int TILE_R = 128;

// Offsets relative to 1024-aligned base
// A: 4 warp slices x (32 rows x 128B SW128) = 16384
static constexpr int OFF_B   = 16384;                 // 7 x (32 krows x 80B) = 17920
static constexpr int B_KSTR  = 2560;
static constexpr int OFF_IDX = OFF_B + 7 * B_KSTR;    // 34304: 896 x i32
static constexpr int OFF_IV  = OFF_IDX + 3584;        // 37888: 896 x f32
static constexpr int SM_TOTAL = OFF_IV + 3584 + 1024; // 42496 (incl. align slack)

__device__ __forceinline__ uint32_t smem_u32(const void* p) {
    uint32_t a;
    asm("{ .reg .u64 t; cvta.to.shared.u64 t, %1; cvt.u32.u64 %0, t; }" : "=r"(a) : "l"(p));
    return a;
}
// pack two f32 -> f16x2 (first arg -> bits[15:0], second -> bits[31:16]), round-nearest
__device__ __forceinline__ uint32_t pack_f16x2(float lo_half, float hi_half) {
    uint32_t r;
    asm("cvt.rn.f16x2.f32 %0, %1, %2;" : "=r"(r) : "f"(hi_half), "f"(lo_half));
    return r;
}
// SW128 swizzle of a byte offset relative to a 1024-aligned tile base
__device__ __forceinline__ uint32_t swz(uint32_t b) { return b ^ ((b >> 3) & 0x70u); }

__device__ __forceinline__ void ldmA(uint32_t* r, uint32_t addr) {
    asm volatile("ldmatrix.sync.aligned.m8n8.x4.shared.b16 {%0,%1,%2,%3}, [%4];"
                 : "=r"(r[0]), "=r"(r[1]), "=r"(r[2]), "=r"(r[3]) : "r"(addr));
}
__device__ __forceinline__ void ldmBT(uint32_t* r, uint32_t addr) {
    asm volatile("ldmatrix.sync.aligned.m8n8.x4.trans.shared.b16 {%0,%1,%2,%3}, [%4];"
                 : "=r"(r[0]), "=r"(r[1]), "=r"(r[2]), "=r"(r[3]) : "r"(addr));
}
__device__ __forceinline__ void mma16816(float* c, const uint32_t* a, uint32_t b0, uint32_t b1) {
    asm volatile(
        "mma.sync.aligned.m16n8k16.row.col.f32.f16.f16.f32 "
        "{%0,%1,%2,%3}, {%4,%5,%6,%7}, {%8,%9}, {%0,%1,%2,%3};"
        : "+f"(c[0]), "+f"(c[1]), "+f"(c[2]), "+f"(c[3])
        : "r"(a[0]), "r"(a[1]), "r"(a[2]), "r"(a[3]), "r"(b0), "r"(b1));
}

__global__ void __launch_bounds__(128)
gfc_hmma_kernel(const float* __restrict__ x,
                const float* __restrict__ w,
                const float* __restrict__ bias,
                const int*   __restrict__ idxl,
                const float* __restrict__ ivv,
                float*       __restrict__ out)
{
    extern __shared__ char smem_raw[];
    const uint32_t sb = smem_u32(smem_raw);
    const uint32_t aA = (sb + 1023u) & ~1023u;      // 1024-aligned base
    char* base = smem_raw + (aA - sb);

    const int tid = threadIdx.x;
    const int wid = tid >> 5;
    const int lan = tid & 31;
    const int m0  = blockIdx.x * TILE_R;
    const int n   = blockIdx.y;

    int*   sIdx = (int*)  (base + OFF_IDX);
    float* sIv  = (float*)(base + OFF_IV);

    // --- stage idx / iv (contiguous) ---
    #pragma unroll
    for (int i = tid; i < TILE_R * K_; i += 128) {
        sIdx[i] = idxl[m0 * K_ + i];
        sIv[i]  = ivv [m0 * K_ + i];
    }

    // --- stage B tiles: per k, 32 K-rows (f) x 32 cols (o) fp16, row stride 80B ---
    for (int i = tid; i < K_ * 1024; i += 128) {
        const int k = i >> 10, f = (i >> 5) & 31, o = i & 31;
        const uint16_t hb = (uint16_t)(pack_f16x2(w[i], 0.f) & 0xFFFFu);
        *(uint16_t*)(base + OFF_B + k * B_KSTR + f * 80 + o * 2) = hb;
    }
    __syncthreads();   // B + idx visible to all; ONLY CTA-wide barrier

    // accumulators: acc[mt][nt][4]  (mt: 16-row tiles, nt: 8-col tiles)
    float acc[2][4][4];
    #pragma unroll
    for (int mt = 0; mt < 2; ++mt)
        #pragma unroll
        for (int nt = 0; nt < 4; ++nt)
            #pragma unroll
            for (int e = 0; e < 4; ++e)
                acc[mt][nt][e] = 0.f;

    // per-warp A slice: 32 rows x 128B (two k's per row: [k_even | k_odd] fp16)
    const uint32_t slice = aA + (uint32_t)(wid << 12);
    char* sliceP = base + (wid << 12);

    // gather mapping: lane = q*8 + r8 (q: 8-float chunk, r8: row mod 8)
    const int q  = lan >> 3;
    const int r8 = lan & 7;
    const float4* x4 = reinterpret_cast<const float4*>(x);
    const int xb = n * (M_ * 8);

    for (int kk = 0; kk < 4; ++kk) {
        // --- gather + convert + store (warp-local rows wid*32..+31) ---
        #pragma unroll
        for (int h = 0; h < 2; ++h) {
            const int k = kk * 2 + h;
            if (k >= K_) break;
            float4 va[4], vb[4];
            float  sc[4];
            #pragma unroll
            for (int rr = 0; rr < 4; ++rr) {
                const int r = r8 + (rr << 3);             // local row 0..31
                const int gr = (wid << 5) + r;            // CTA row
                const int src = sIdx[gr * K_ + k];
                sc[rr] = sIv[gr * K_ + k];
                const float4* p = x4 + xb + src * 8 + q * 2;
                va[rr] = __ldg(p);
                vb[rr] = __ldg(p + 1);
            }
            #pragma unroll
            for (int rr = 0; rr < 4; ++rr) {
                const int r = r8 + (rr << 3);
                const float s = sc[rr];
                uint4 pk;
                pk.x = pack_f16x2(va[rr].x * s, va[rr].y * s);
                pk.y = pack_f16x2(va[rr].z * s, va[rr].w * s);
                pk.z = pack_f16x2(vb[rr].x * s, vb[rr].y * s);
                pk.w = pack_f16x2(vb[rr].z * s, vb[rr].w * s);
                // row r, k-half h, f-cols 8q..8q+7 -> bytes h*64 + 16q
                *(uint4*)(sliceP + swz((uint32_t)(r << 7) + (uint32_t)(h << 6) + (uint32_t)(q << 4))) = pk;
            }
        }
        __syncwarp();

        // --- warp GEMM over this kk's K16 chunks ---
        const int ncc = (kk == 3) ? 2 : 4;   // kk=3 holds only k=6 (cols 0..31)
        #pragma unroll 4
        for (int cc = 0; cc < ncc; ++cc) {
            const int kv = kk * 2 + (cc >> 1);          // which k this chunk belongs to
            const uint32_t cb = (uint32_t)(cc * 32 + ((lan >> 4) << 4));
            uint32_t A0[4], A1[4];
            ldmA(A0, slice + swz((uint32_t)((lan & 15) << 7) + cb));
            ldmA(A1, slice + swz((uint32_t)(((lan & 15) + 16) << 7) + cb));

            const uint32_t bk = aA + OFF_B + (uint32_t)(kv * B_KSTR);
            const int krow = ((cc & 1) << 4) + (lan & 7) + (((lan >> 3) & 1) << 3);
            const int nc0  = (lan >> 4) << 3;
            uint32_t B0[4], B1[4];
            ldmBT(B0, bk + krow * 80 + nc0 * 2);          // n 0..15
            ldmBT(B1, bk + krow * 80 + (16 + nc0) * 2);   // n 16..31

            mma16816(acc[0][0], A0, B0[0], B0[1]);
            mma16816(acc[0][1], A0, B0[2], B0[3]);
            mma16816(acc[0][2], A0, B1[0], B1[1]);
            mma16816(acc[0][3], A0, B1[2], B1[3]);
            mma16816(acc[1][0], A1, B0[0], B0[1]);
            mma16816(acc[1][1], A1, B0[2], B0[3]);
            mma16816(acc[1][2], A1, B1[0], B1[1]);
            mma16816(acc[1][3], A1, B1[2], B1[3]);
        }
        __syncwarp();   // ldmatrix reads done before next kk overwrites slice
    }

    // --- epilogue: fragment layout -> global f32 + bias ---
    const int quad = lan >> 2;           // row within 8
    const int tq   = lan & 3;            // col pair
    float2 bv[4];
    const float2* b2 = reinterpret_cast<const float2*>(bias);
    #pragma unroll
    for (int nt = 0; nt < 4; ++nt) bv[nt] = __ldg(b2 + nt * 4 + tq);

    #pragma unroll
    for (int mt = 0; mt < 2; ++mt) {
        const int r0 = m0 + (wid << 5) + mt * 16 + quad;
        #pragma unroll
        for (int nt = 0; nt < 4; ++nt) {
            float2 v0, v1;
            v0.x = acc[mt][nt][0] + bv[nt].x;
            v0.y = acc[mt][nt][1] + bv[nt].y;
            v1.x = acc[mt][nt][2] + bv[nt].x;
            v1.y = acc[mt][nt][3] + bv[nt].y;
            const int c = nt * 8 + tq * 2;
            *reinterpret_cast<float2*>(out + ((size_t)(n * M_ + r0)) * 32 + c)     = v0;
            *reinterpret_cast<float2*>(out + ((size_t)(n * M_ + r0 + 8)) * 32 + c) = v1;
        }
    }
}

extern "C" void kernel_launch(void* const* d_in, const int* in_sizes, int n_in,
                              void* d_out, int out_size)
{
    const float* x    = (const float*)d_in[0];   // (16, 65536, 32) f32
    const float* wgt  = (const float*)d_in[1];   // (7, 32, 32) f32
    const float* bias = (const float*)d_in[2];   // (32,) f32
    const int*   idx  = (const int*)  d_in[3];   // (65536*7,) i32
    const float* iv   = (const float*)d_in[4];   // (65536, 7) f32
    float* out = (float*)d_out;                  // (16, 65536, 32) f32

    cudaFuncSetAttribute(gfc_hmma_kernel,
                         cudaFuncAttributeMaxDynamicSharedMemorySize, SM_TOTAL);
    dim3 grid(M_ / TILE_R, N_, 1);               // (512, 16)
    gfc_hmma_kernel<<<grid, 128, SM_TOTAL>>>(x, wgt, bias, idx, iv, out);
}

// round 7
// speedup vs baseline: 3.4356x; 3.4356x over previous
#include <cuda_runtime.h>
#include <cuda_fp16.h>
#include <cstdint>

// out[n,m,o] = sum_k sum_f x[n, idx[m,k], f] * iv[m,k] * W[k,f,o] + bias[o]
// N=16, M=65536, FIN=FOUT=32, K=7
static constexpr int N_ = 16, M_ = 65536, K_ = 7;
static constexpr int TILE_R = 128;

__device__ __forceinline__ uint32_t smem_u32(const void* p) {
    uint32_t a;
    asm("{ .reg .u64 t; cvta.to.shared.u64 t, %1; cvt.u32.u64 %0, t; }" : "=r"(a) : "l"(p));
    return a;
}
// pack two f32 -> f16x2 (first arg -> bits[15:0], second -> bits[31:16]), round-nearest
__device__ __forceinline__ uint32_t pack_f16x2(float lo_half, float hi_half) {
    uint32_t r;
    asm("cvt.rn.f16x2.f32 %0, %1, %2;" : "=r"(r) : "f"(hi_half), "f"(lo_half));
    return r;
}
__device__ __forceinline__ void ldmBT(uint32_t* r, uint32_t addr) {
    asm volatile("ldmatrix.sync.aligned.m8n8.x4.trans.shared.b16 {%0,%1,%2,%3}, [%4];"
                 : "=r"(r[0]), "=r"(r[1]), "=r"(r[2]), "=r"(r[3]) : "r"(addr));
}
__device__ __forceinline__ void mma16816(float* c, const uint32_t* a, uint32_t b0, uint32_t b1) {
    asm volatile(
        "mma.sync.aligned.m16n8k16.row.col.f32.f16.f16.f32 "
        "{%0,%1,%2,%3}, {%4,%5,%6,%7}, {%8,%9}, {%0,%1,%2,%3};"
        : "+f"(c[0]), "+f"(c[1]), "+f"(c[2]), "+f"(c[3])
        : "r"(a[0]), "r"(a[1]), "r"(a[2]), "r"(a[3]), "r"(b0), "r"(b1));
}
// B storage-row permutation: A frag slot for lane c holds storage f {4c..4c+3};
// mma pairs it with B-frag k-rows {2c,2c+1} (b0) and {2c+8,2c+9} (b1).
// So B storage row r must hold W f = 4*((r&7)>>1) + 2*((r&15)>>3) + (r&1) (+16 for 2nd chunk).
__device__ __forceinline__ int fperm(int r) {
    const int b = r & 15;
    return (r & 16) + 4 * ((b & 7) >> 1) + 2 * (b >> 3) + (b & 1);
}

__global__ void __launch_bounds__(128, 4)
gfc_hmma_kernel(const float* __restrict__ x,
                const float* __restrict__ w,
                const float* __restrict__ bias,
                const int*   __restrict__ idxl,
                const float* __restrict__ ivv,
                float*       __restrict__ out)
{
    __shared__ __align__(128) uint8_t Bsm[K_ * 2560];   // per k: 32 krows x 80B fp16
    __shared__ int2 sPair[TILE_R * K_];                 // (idx, iv) pairs

    const int tid = threadIdx.x;
    const int wid = tid >> 5;
    const int lan = tid & 31;
    const int q   = lan >> 2;     // fragment row quad
    const int c   = lan & 3;      // fragment k-group
    const int m0  = blockIdx.x * TILE_R;
    const int n   = blockIdx.y;

    // --- stage (idx, iv) pairs ---
    #pragma unroll
    for (int i = tid; i < TILE_R * K_; i += 128)
        sPair[i] = make_int2(idxl[m0 * K_ + i], __float_as_int(ivv[m0 * K_ + i]));

    // --- stage B with k-permuted storage rows ---
    for (int i = tid; i < K_ * 1024; i += 128) {
        const int k = i >> 10, r = (i >> 5) & 31, o = i & 31;
        const float v = w[(k << 10) + fperm(r) * 32 + o];
        *(uint16_t*)(Bsm + k * 2560 + r * 80 + o * 2) =
            (uint16_t)(pack_f16x2(v, 0.f) & 0xFFFFu);
    }
    __syncthreads();   // only CTA-wide barrier

    float acc[2][4][4];
    #pragma unroll
    for (int mt = 0; mt < 2; ++mt)
        #pragma unroll
        for (int nt = 0; nt < 4; ++nt)
            #pragma unroll
            for (int e = 0; e < 4; ++e)
                acc[mt][nt][e] = 0.f;

    const uint32_t bbase = smem_u32(Bsm);
    const float4* x4 = reinterpret_cast<const float4*>(x);
    const int xb = n * (M_ * 8);
    const int rbase = (wid << 5) + q;      // local rows: rbase + 8t, t=0..3
    const int nc0 = (lan >> 4) << 3;
    const int krow = lan & 15;

    #pragma unroll 1
    for (int k = 0; k < K_; ++k) {
        // (idx, iv) for the 4 rows this lane owns (broadcast across 4 c-lanes)
        int2 pr[4];
        #pragma unroll
        for (int t = 0; t < 4; ++t)
            pr[t] = sPair[(rbase + (t << 3)) * K_ + k];

        // gather: 8 independent LDG.128 straight into fragment-source registers
        float4 g[4][2];
        #pragma unroll
        for (int t = 0; t < 4; ++t) {
            const float4* p = x4 + xb + pr[t].x * 8;
            g[t][0] = __ldg(p + c);        // storage f [4c..4c+3]
            g[t][1] = __ldg(p + 4 + c);    // storage f [16+4c..16+4c+3]
        }

        // B fragments for both K16 chunks, both n-halves
        const uint32_t bk = bbase + k * 2560;
        uint32_t Ba[4], Bb[4], Bc[4], Bd[4];
        ldmBT(Ba, bk + krow * 80 + nc0 * 2);              // cc0, n 0..15
        ldmBT(Bb, bk + krow * 80 + (16 + nc0) * 2);       // cc0, n 16..31
        ldmBT(Bc, bk + (16 + krow) * 80 + nc0 * 2);       // cc1, n 0..15
        ldmBT(Bd, bk + (16 + krow) * 80 + (16 + nc0) * 2);// cc1, n 16..31

        float s[4];
        #pragma unroll
        for (int t = 0; t < 4; ++t) s[t] = __int_as_float(pr[t].y);

        #pragma unroll
        for (int cc = 0; cc < 2; ++cc) {
            #pragma unroll
            for (int mt = 0; mt < 2; ++mt) {
                const int t0 = 2 * mt, t1 = 2 * mt + 1;   // rows q+16mt, q+8+16mt
                uint32_t a[4];
                a[0] = pack_f16x2(g[t0][cc].x * s[t0], g[t0][cc].y * s[t0]);
                a[1] = pack_f16x2(g[t1][cc].x * s[t1], g[t1][cc].y * s[t1]);
                a[2] = pack_f16x2(g[t0][cc].z * s[t0], g[t0][cc].w * s[t0]);
                a[3] = pack_f16x2(g[t1][cc].z * s[t1], g[t1][cc].w * s[t1]);
                const uint32_t* Bn0 = cc ? Bc : Ba;
                const uint32_t* Bn1 = cc ? Bd : Bb;
                mma16816(acc[mt][0], a, Bn0[0], Bn0[1]);
                mma16816(acc[mt][1], a, Bn0[2], Bn0[3]);
                mma16816(acc[mt][2], a, Bn1[0], Bn1[1]);
                mma16816(acc[mt][3], a, Bn1[2], Bn1[3]);
            }
        }
    }

    // --- epilogue: fragment -> global f32 + bias ---
    float2 bv[4];
    const float2* b2 = reinterpret_cast<const float2*>(bias);
    #pragma unroll
    for (int nt = 0; nt < 4; ++nt) bv[nt] = __ldg(b2 + nt * 4 + c);

    #pragma unroll
    for (int mt = 0; mt < 2; ++mt) {
        const int r0 = m0 + (wid << 5) + mt * 16 + q;
        #pragma unroll
        for (int nt = 0; nt < 4; ++nt) {
            float2 v0, v1;
            v0.x = acc[mt][nt][0] + bv[nt].x;
            v0.y = acc[mt][nt][1] + bv[nt].y;
            v1.x = acc[mt][nt][2] + bv[nt].x;
            v1.y = acc[mt][nt][3] + bv[nt].y;
            const int col = nt * 8 + c * 2;
            *reinterpret_cast<float2*>(out + ((size_t)(n * M_ + r0)) * 32 + col)     = v0;
            *reinterpret_cast<float2*>(out + ((size_t)(n * M_ + r0 + 8)) * 32 + col) = v1;
        }
    }
}

extern "C" void kernel_launch(void* const* d_in, const int* in_sizes, int n_in,
                              void* d_out, int out_size)
{
    const float* x    = (const float*)d_in[0];   // (16, 65536, 32) f32
    const float* wgt  = (const float*)d_in[1];   // (7, 32, 32) f32
    const float* bias = (const float*)d_in[2];   // (32,) f32
    const int*   idx  = (const int*)  d_in[3];   // (65536*7,) i32
    const float* iv   = (const float*)d_in[4];   // (65536, 7) f32
    float* out = (float*)d_out;                  // (16, 65536, 32) f32

    dim3 grid(M_ / TILE_R, N_, 1);               // (512, 16)
    gfc_hmma_kernel<<<grid, 128>>>(x, wgt, bias, idx, iv, out);
}